// round 3
// baseline (speedup 1.0000x reference)
#include <cuda_runtime.h>
#include <cuda_bf16.h>
#include <math.h>

// Problem constants
#define BB 4
#define SS 1024
#define EE 1024
#define DD 1024
#define HH 16
#define DHH 64
#define DFF 4096
#define LN_EPS 1e-6f

// ----------------------------------------------------------------------------
// Scratch (static device globals; no allocations allowed)
// ----------------------------------------------------------------------------
__device__ float g_q   [BB * SS * DD];         // 4.19M
__device__ float g_k   [BB * EE * DD];
__device__ float g_v   [BB * EE * DD];
__device__ float g_ctx [BB * SS * DD];
__device__ float g_t0  [BB * SS * DD];
__device__ float g_x1  [BB * SS * DD];
__device__ float g_y   [BB * SS * DD];
__device__ float g_ffn [BB * SS * DFF];        // 16.8M
__device__ float g_scores[(size_t)BB * HH * SS * SS];  // 67.1M (268MB)

// ----------------------------------------------------------------------------
// GEMM: C[M,N] = A[M,K] @ B[K,N] + bias[N], optional ReLU.
// 128x128 tile, BK=16, 256 threads, 8x8 per thread.
// M,N,K are multiples of 128/128/16 in all uses here.
// ----------------------------------------------------------------------------
#define GBM 128
#define GBN 128
#define GBK 16

template <int RELU>
__global__ __launch_bounds__(256, 2) void gemm_bias_kernel(
    const float* __restrict__ A, const float* __restrict__ B,
    const float* __restrict__ bias, float* __restrict__ C,
    int M, int N, int K)
{
    __shared__ float As[GBK][GBM];   // transposed: As[k][m]
    __shared__ float Bs[GBK][GBN];

    const int tid = threadIdx.x;           // 0..255
    const int tx = tid & 15;               // 0..15
    const int ty = tid >> 4;               // 0..15
    const int bx = blockIdx.x;             // N tile
    const int by = blockIdx.y;             // M tile

    float acc[8][8];
#pragma unroll
    for (int i = 0; i < 8; i++)
#pragma unroll
        for (int j = 0; j < 8; j++) acc[i][j] = 0.f;

    for (int k0 = 0; k0 < K; k0 += GBK) {
        // Load A tile (128 x 16) as float4, store transposed
#pragma unroll
        for (int l = 0; l < 2; l++) {
            int idx = tid + l * 256;              // 0..511 float4 slots
            int m   = idx >> 2;                   // 0..127
            int kk4 = (idx & 3) << 2;             // 0,4,8,12
            float4 a4 = *reinterpret_cast<const float4*>(
                &A[(size_t)(by * GBM + m) * K + k0 + kk4]);
            As[kk4 + 0][m] = a4.x;
            As[kk4 + 1][m] = a4.y;
            As[kk4 + 2][m] = a4.z;
            As[kk4 + 3][m] = a4.w;
        }
        // Load B tile (16 x 128) as float4
#pragma unroll
        for (int l = 0; l < 2; l++) {
            int idx = tid + l * 256;
            int kk  = idx >> 5;                   // 0..15
            int n4  = (idx & 31) << 2;            // 0..124
            *reinterpret_cast<float4*>(&Bs[kk][n4]) =
                *reinterpret_cast<const float4*>(
                    &B[(size_t)(k0 + kk) * N + bx * GBN + n4]);
        }
        __syncthreads();

#pragma unroll
        for (int kk = 0; kk < GBK; kk++) {
            float a[8], b[8];
            float4 a0 = *reinterpret_cast<const float4*>(&As[kk][ty * 8]);
            float4 a1 = *reinterpret_cast<const float4*>(&As[kk][ty * 8 + 4]);
            float4 b0 = *reinterpret_cast<const float4*>(&Bs[kk][tx * 8]);
            float4 b1 = *reinterpret_cast<const float4*>(&Bs[kk][tx * 8 + 4]);
            a[0]=a0.x; a[1]=a0.y; a[2]=a0.z; a[3]=a0.w;
            a[4]=a1.x; a[5]=a1.y; a[6]=a1.z; a[7]=a1.w;
            b[0]=b0.x; b[1]=b0.y; b[2]=b0.z; b[3]=b0.w;
            b[4]=b1.x; b[5]=b1.y; b[6]=b1.z; b[7]=b1.w;
#pragma unroll
            for (int i = 0; i < 8; i++)
#pragma unroll
                for (int j = 0; j < 8; j++)
                    acc[i][j] = fmaf(a[i], b[j], acc[i][j]);
        }
        __syncthreads();
    }

    // Epilogue: bias (+ optional relu)
    const int colBase = bx * GBN + tx * 8;
    float bias0[8];
#pragma unroll
    for (int j = 0; j < 8; j++) bias0[j] = bias[colBase + j];

#pragma unroll
    for (int i = 0; i < 8; i++) {
        int row = by * GBM + ty * 8 + i;
        float4 o0, o1;
        float r[8];
#pragma unroll
        for (int j = 0; j < 8; j++) {
            float vv = acc[i][j] + bias0[j];
            if (RELU) vv = fmaxf(vv, 0.f);
            r[j] = vv;
        }
        o0.x=r[0]; o0.y=r[1]; o0.z=r[2]; o0.w=r[3];
        o1.x=r[4]; o1.y=r[5]; o1.z=r[6]; o1.w=r[7];
        *reinterpret_cast<float4*>(&C[(size_t)row * N + colBase])     = o0;
        *reinterpret_cast<float4*>(&C[(size_t)row * N + colBase + 4]) = o1;
    }
}

// ----------------------------------------------------------------------------
// Attention scores: S[bh, q, k] = (Q_bh . K_bh) * 0.125 + mask * (-1e9)
// Q flat: [B*Sq, D] with head h at cols h*64..h*64+63. K flat: [B*Skv, D].
// mask_mode 0: causal[q*Skv + k] ; mask_mode 1: pmask[b*Skv + k]
// grid: (Sq/64, Skv/64, B*H), block 256, 4x4 per thread.
// ----------------------------------------------------------------------------
__global__ __launch_bounds__(256) void attn_scores_kernel(
    const float* __restrict__ Qf, const float* __restrict__ Kf,
    const float* __restrict__ mptr, int mask_mode,
    float* __restrict__ Sout, int Sq, int Skv)
{
    __shared__ float Qs[64][65];
    __shared__ float Ks[64][65];

    const int tid = threadIdx.x;
    const int tx = tid & 15, ty = tid >> 4;
    const int bh = blockIdx.z;
    const int b = bh / HH, h = bh % HH;
    const int q0 = blockIdx.x * 64;
    const int k0 = blockIdx.y * 64;

    // Load Q tile: (qi, d) 64x64  -> 1024 float4 / 256 thr = 4 each
#pragma unroll
    for (int l = 0; l < 4; l++) {
        int idx = tid + l * 256;           // 0..1023
        int qi = idx >> 4;                 // 0..63
        int d4 = (idx & 15) << 2;          // 0..60
        float4 v4 = *reinterpret_cast<const float4*>(
            &Qf[(size_t)(b * Sq + q0 + qi) * DD + h * DHH + d4]);
        Qs[qi][d4+0]=v4.x; Qs[qi][d4+1]=v4.y; Qs[qi][d4+2]=v4.z; Qs[qi][d4+3]=v4.w;
    }
#pragma unroll
    for (int l = 0; l < 4; l++) {
        int idx = tid + l * 256;
        int ki = idx >> 4;
        int d4 = (idx & 15) << 2;
        float4 v4 = *reinterpret_cast<const float4*>(
            &Kf[(size_t)(b * Skv + k0 + ki) * DD + h * DHH + d4]);
        Ks[ki][d4+0]=v4.x; Ks[ki][d4+1]=v4.y; Ks[ki][d4+2]=v4.z; Ks[ki][d4+3]=v4.w;
    }
    __syncthreads();

    float acc[4][4];
#pragma unroll
    for (int i = 0; i < 4; i++)
#pragma unroll
        for (int j = 0; j < 4; j++) acc[i][j] = 0.f;

#pragma unroll 8
    for (int d = 0; d < 64; d++) {
        float a[4], bv[4];
#pragma unroll
        for (int i = 0; i < 4; i++) a[i]  = Qs[ty * 4 + i][d];
#pragma unroll
        for (int j = 0; j < 4; j++) bv[j] = Ks[tx * 4 + j][d];
#pragma unroll
        for (int i = 0; i < 4; i++)
#pragma unroll
            for (int j = 0; j < 4; j++)
                acc[i][j] = fmaf(a[i], bv[j], acc[i][j]);
    }

#pragma unroll
    for (int i = 0; i < 4; i++) {
        int q = q0 + ty * 4 + i;
#pragma unroll
        for (int j = 0; j < 4; j++) {
            int k = k0 + tx * 4 + j;
            float m = (mask_mode == 0) ? mptr[(size_t)q * Skv + k]
                                       : mptr[(size_t)b * Skv + k];
            Sout[((size_t)bh * Sq + q) * Skv + k] = acc[i][j] * 0.125f + m * (-1e9f);
        }
    }
}

// ----------------------------------------------------------------------------
// Row softmax, ncols = 1024. One warp per row. blockDim = (32, 8).
// ----------------------------------------------------------------------------
__global__ __launch_bounds__(256) void softmax_rows_kernel(
    float* __restrict__ P, int nrows)
{
    int row = blockIdx.x * 8 + threadIdx.y;
    if (row >= nrows) return;
    float* p = P + (size_t)row * 1024;
    const int lane = threadIdx.x;

    float v[32];
    float mx = -INFINITY;
#pragma unroll
    for (int i = 0; i < 32; i++) {
        v[i] = p[lane + i * 32];
        mx = fmaxf(mx, v[i]);
    }
#pragma unroll
    for (int o = 16; o; o >>= 1) mx = fmaxf(mx, __shfl_xor_sync(0xffffffffu, mx, o));

    float sum = 0.f;
#pragma unroll
    for (int i = 0; i < 32; i++) {
        v[i] = __expf(v[i] - mx);
        sum += v[i];
    }
#pragma unroll
    for (int o = 16; o; o >>= 1) sum += __shfl_xor_sync(0xffffffffu, sum, o);
    float inv = 1.f / sum;
#pragma unroll
    for (int i = 0; i < 32; i++) p[lane + i * 32] = v[i] * inv;
}

// ----------------------------------------------------------------------------
// ctx[b, q, h*64 + d] = sum_k P[bh, q, k] * V[b*Skv + k, h*64 + d]
// grid: (Sq/64, B*H), block 256, 4x4 per thread over a 64(q) x 64(d) tile.
// ----------------------------------------------------------------------------
__global__ __launch_bounds__(256) void attn_v_kernel(
    const float* __restrict__ P, const float* __restrict__ Vf,
    float* __restrict__ ctx, int Sq, int Skv)
{
    __shared__ float Ps[64][65];
    __shared__ float Vs[64][65];

    const int tid = threadIdx.x;
    const int tx = tid & 15, ty = tid >> 4;
    const int bh = blockIdx.y;
    const int b = bh / HH, h = bh % HH;
    const int q0 = blockIdx.x * 64;

    float acc[4][4];
#pragma unroll
    for (int i = 0; i < 4; i++)
#pragma unroll
        for (int j = 0; j < 4; j++) acc[i][j] = 0.f;

    for (int kv = 0; kv < Skv; kv += 64) {
#pragma unroll
        for (int l = 0; l < 4; l++) {
            int idx = tid + l * 256;
            int qi = idx >> 4;
            int k4 = (idx & 15) << 2;
            float4 v4 = *reinterpret_cast<const float4*>(
                &P[((size_t)bh * Sq + q0 + qi) * Skv + kv + k4]);
            Ps[qi][k4+0]=v4.x; Ps[qi][k4+1]=v4.y; Ps[qi][k4+2]=v4.z; Ps[qi][k4+3]=v4.w;
        }
#pragma unroll
        for (int l = 0; l < 4; l++) {
            int idx = tid + l * 256;
            int ki = idx >> 4;
            int d4 = (idx & 15) << 2;
            float4 v4 = *reinterpret_cast<const float4*>(
                &Vf[(size_t)(b * Skv + kv + ki) * DD + h * DHH + d4]);
            Vs[ki][d4+0]=v4.x; Vs[ki][d4+1]=v4.y; Vs[ki][d4+2]=v4.z; Vs[ki][d4+3]=v4.w;
        }
        __syncthreads();

#pragma unroll 8
        for (int kk = 0; kk < 64; kk++) {
            float a[4], bv[4];
#pragma unroll
            for (int i = 0; i < 4; i++) a[i]  = Ps[ty * 4 + i][kk];
#pragma unroll
            for (int j = 0; j < 4; j++) bv[j] = Vs[kk][tx * 4 + j];
#pragma unroll
            for (int i = 0; i < 4; i++)
#pragma unroll
                for (int j = 0; j < 4; j++)
                    acc[i][j] = fmaf(a[i], bv[j], acc[i][j]);
        }
        __syncthreads();
    }

#pragma unroll
    for (int i = 0; i < 4; i++) {
        int q = q0 + ty * 4 + i;
#pragma unroll
        for (int j = 0; j < 4; j++)
            ctx[(size_t)(b * Sq + q) * DD + h * DHH + tx * 4 + j] = acc[i][j];
    }
}

// ----------------------------------------------------------------------------
// out[row,:] = LayerNorm(a[row,:] + b[row,:]) * g + beta   (D = 1024)
// One block (256 threads) per row.
// ----------------------------------------------------------------------------
__global__ __launch_bounds__(256) void add_ln_kernel(
    const float* __restrict__ a, const float* __restrict__ b,
    const float* __restrict__ g, const float* __restrict__ be,
    float* __restrict__ o)
{
    const int row = blockIdx.x;
    const int tid = threadIdx.x;
    const float* pa = a + (size_t)row * DD;
    const float* pb = b + (size_t)row * DD;

    __shared__ float red[8];
    float v[4];
    float s = 0.f;
#pragma unroll
    for (int i = 0; i < 4; i++) {
        int c = tid + i * 256;
        v[i] = pa[c] + pb[c];
        s += v[i];
    }
#pragma unroll
    for (int o2 = 16; o2; o2 >>= 1) s += __shfl_xor_sync(0xffffffffu, s, o2);
    if ((tid & 31) == 0) red[tid >> 5] = s;
    __syncthreads();
    if (tid < 32) {
        float t = (tid < 8) ? red[tid] : 0.f;
#pragma unroll
        for (int o2 = 4; o2; o2 >>= 1) t += __shfl_xor_sync(0xffffffffu, t, o2);
        if (tid == 0) red[0] = t;
    }
    __syncthreads();
    const float mu = red[0] * (1.f / 1024.f);
    __syncthreads();

    float s2 = 0.f;
#pragma unroll
    for (int i = 0; i < 4; i++) {
        float d = v[i] - mu;
        s2 += d * d;
    }
#pragma unroll
    for (int o2 = 16; o2; o2 >>= 1) s2 += __shfl_xor_sync(0xffffffffu, s2, o2);
    if ((tid & 31) == 0) red[tid >> 5] = s2;
    __syncthreads();
    if (tid < 32) {
        float t = (tid < 8) ? red[tid] : 0.f;
#pragma unroll
        for (int o2 = 4; o2; o2 >>= 1) t += __shfl_xor_sync(0xffffffffu, t, o2);
        if (tid == 0) red[0] = t;
    }
    __syncthreads();
    const float rstd = rsqrtf(red[0] * (1.f / 1024.f) + LN_EPS);

#pragma unroll
    for (int i = 0; i < 4; i++) {
        int c = tid + i * 256;
        o[(size_t)row * DD + c] = (v[i] - mu) * rstd * g[c] + be[c];
    }
}

// ----------------------------------------------------------------------------
// Host launch
// ----------------------------------------------------------------------------
static void launch_gemm(const float* A, const float* B, const float* bias,
                        float* C, int M, int N, int K, bool relu)
{
    dim3 grid(N / GBN, M / GBM);
    if (relu)
        gemm_bias_kernel<1><<<grid, 256>>>(A, B, bias, C, M, N, K);
    else
        gemm_bias_kernel<0><<<grid, 256>>>(A, B, bias, C, M, N, K);
}

extern "C" void kernel_launch(void* const* d_in, const int* in_sizes, int n_in,
                              void* d_out, int out_size)
{
    const float* x      = (const float*)d_in[0];   // [B,S,D]
    const float* enc    = (const float*)d_in[1];   // [B,E,D]
    const float* causal = (const float*)d_in[2];   // [1,1,S,S]
    const float* pmask  = (const float*)d_in[3];   // [B,1,1,E]

    const float* m1_wq = (const float*)d_in[4];
    const float* m1_qb = (const float*)d_in[5];
    const float* m1_wk = (const float*)d_in[6];
    const float* m1_kb = (const float*)d_in[7];
    const float* m1_wv = (const float*)d_in[8];
    const float* m1_vb = (const float*)d_in[9];
    const float* m1_wo = (const float*)d_in[10];
    const float* m1_ob = (const float*)d_in[11];

    const float* m2_wq = (const float*)d_in[12];
    const float* m2_qb = (const float*)d_in[13];
    const float* m2_wk = (const float*)d_in[14];
    const float* m2_kb = (const float*)d_in[15];
    const float* m2_wv = (const float*)d_in[16];
    const float* m2_vb = (const float*)d_in[17];
    const float* m2_wo = (const float*)d_in[18];
    const float* m2_ob = (const float*)d_in[19];

    const float* ffn_w1 = (const float*)d_in[20];
    const float* ffn_b1 = (const float*)d_in[21];
    const float* ffn_w2 = (const float*)d_in[22];
    const float* ffn_b2 = (const float*)d_in[23];

    const float* ln1_g = (const float*)d_in[24];
    const float* ln1_b = (const float*)d_in[25];
    const float* ln2_g = (const float*)d_in[26];
    const float* ln2_b = (const float*)d_in[27];
    const float* ln3_g = (const float*)d_in[28];
    const float* ln3_b = (const float*)d_in[29];

    float* out = (float*)d_out;

    float *q, *k, *v, *ctx, *t0, *x1, *y, *ffn, *scores;
    cudaGetSymbolAddress((void**)&q,      g_q);
    cudaGetSymbolAddress((void**)&k,      g_k);
    cudaGetSymbolAddress((void**)&v,      g_v);
    cudaGetSymbolAddress((void**)&ctx,    g_ctx);
    cudaGetSymbolAddress((void**)&t0,     g_t0);
    cudaGetSymbolAddress((void**)&x1,     g_x1);
    cudaGetSymbolAddress((void**)&y,      g_y);
    cudaGetSymbolAddress((void**)&ffn,    g_ffn);
    cudaGetSymbolAddress((void**)&scores, g_scores);

    const size_t OUTN = (size_t)BB * SS * DD;            // 4,194,304
    const size_t ATT  = (size_t)BB * HH * SS * SS;       // 67,108,864
    float* attn1 = ((size_t)out_size >= OUTN + ATT)      ? out + OUTN        : scores;
    float* attn2 = ((size_t)out_size >= OUTN + 2 * ATT)  ? out + OUTN + ATT  : scores;

    const int BS = BB * SS;   // 4096 rows
    const int BE = BB * EE;   // 4096 rows
    const int nrowsAttn = BB * HH * SS;  // 65536

    // ---------------- MHA1 (masked self-attention) ----------------
    launch_gemm(x, m1_wq, m1_qb, q, BS, DD, DD, false);
    launch_gemm(x, m1_wk, m1_kb, k, BS, DD, DD, false);
    launch_gemm(x, m1_wv, m1_vb, v, BS, DD, DD, false);

    attn_scores_kernel<<<dim3(SS / 64, SS / 64, BB * HH), 256>>>(
        q, k, causal, /*mask_mode=*/0, attn1, SS, SS);
    softmax_rows_kernel<<<nrowsAttn / 8, dim3(32, 8)>>>(attn1, nrowsAttn);
    attn_v_kernel<<<dim3(SS / 64, BB * HH), 256>>>(attn1, v, ctx, SS, SS);

    launch_gemm(ctx, m1_wo, m1_ob, t0, BS, DD, DD, false);
    add_ln_kernel<<<BS, 256>>>(x, t0, ln1_g, ln1_b, x1);

    // ---------------- MHA2 (cross-attention) ----------------
    launch_gemm(x1,  m2_wq, m2_qb, q, BS, DD, DD, false);
    launch_gemm(enc, m2_wk, m2_kb, k, BE, DD, DD, false);
    launch_gemm(enc, m2_wv, m2_vb, v, BE, DD, DD, false);

    attn_scores_kernel<<<dim3(SS / 64, EE / 64, BB * HH), 256>>>(
        q, k, pmask, /*mask_mode=*/1, attn2, SS, EE);
    softmax_rows_kernel<<<nrowsAttn / 8, dim3(32, 8)>>>(attn2, nrowsAttn);
    attn_v_kernel<<<dim3(SS / 64, BB * HH), 256>>>(attn2, v, ctx, SS, EE);

    launch_gemm(ctx, m2_wo, m2_ob, t0, BS, DD, DD, false);
    add_ln_kernel<<<BS, 256>>>(t0, x1, ln2_g, ln2_b, y);

    // ---------------- FFN ----------------
    launch_gemm(y, ffn_w1, ffn_b1, ffn, BS, DFF, DD, true);
    launch_gemm(ffn, ffn_w2, ffn_b2, t0, BS, DD, DFF, false);
    add_ln_kernel<<<BS, 256>>>(y, t0, ln3_g, ln3_b, out);
}

// round 4
// speedup vs baseline: 2.9165x; 2.9165x over previous
#include <cuda_runtime.h>
#include <cuda_bf16.h>
#include <math.h>

// Problem constants
#define BB 4
#define SS 1024
#define EE 1024
#define DD 1024
#define HH 16
#define DHH 64
#define DFF 4096
#define LN_EPS 1e-6f

// ----------------------------------------------------------------------------
// Scratch (static device globals; no allocations allowed)
// ----------------------------------------------------------------------------
__device__ float g_q   [BB * SS * DD];
__device__ float g_k   [BB * EE * DD];
__device__ float g_v   [BB * EE * DD];
__device__ float g_ctx [BB * SS * DD];
__device__ float g_t0  [BB * SS * DD];
__device__ float g_x1  [BB * SS * DD];
__device__ float g_y   [BB * SS * DD];
__device__ float g_ffn [BB * SS * DFF];
__device__ float g_scores[(size_t)BB * HH * SS * SS];

// ----------------------------------------------------------------------------
// TF32 mma helpers
// ----------------------------------------------------------------------------
__device__ __forceinline__ unsigned cvt_tf32(float x) {
    unsigned r;
    asm("cvt.rna.tf32.f32 %0, %1;" : "=r"(r) : "f"(x));
    return r;
}

__device__ __forceinline__ void mma_tf32(float* d, const unsigned* a,
                                         const unsigned* b, const float* c) {
    asm("mma.sync.aligned.m16n8k8.row.col.f32.tf32.tf32.f32 "
        "{%0,%1,%2,%3}, {%4,%5,%6,%7}, {%8,%9}, {%10,%11,%12,%13};"
        : "=f"(d[0]), "=f"(d[1]), "=f"(d[2]), "=f"(d[3])
        : "r"(a[0]), "r"(a[1]), "r"(a[2]), "r"(a[3]),
          "r"(b[0]), "r"(b[1]),
          "f"(c[0]), "f"(c[1]), "f"(c[2]), "f"(c[3]));
}

__device__ __forceinline__ void cp_async16(void* smem, const void* gmem) {
    unsigned saddr = (unsigned)__cvta_generic_to_shared(smem);
    asm volatile("cp.async.cg.shared.global [%0], [%1], 16;" :: "r"(saddr), "l"(gmem));
}
#define CP_COMMIT() asm volatile("cp.async.commit_group;")
#define CP_WAIT0()  asm volatile("cp.async.wait_group 0;")

// ----------------------------------------------------------------------------
// TF32 GEMM: C[M,N] = A[M,K] @ B[K,N] + bias[N], optional ReLU.
// 128x128x32 CTA tile, 8 warps (4m x 2n), warp tile 32x64.
// Fragment smem layouts are bank-conflict-free:
//   As stride 36 -> bank (4*row + k) % 32 == lane  (distinct)
//   Bs stride 136 -> bank (8*k + n) % 32 == 8*tig + g (distinct)
// ----------------------------------------------------------------------------
template <int RELU>
__global__ __launch_bounds__(256, 2) void gemm_tf32_kernel(
    const float* __restrict__ A, const float* __restrict__ B,
    const float* __restrict__ bias, float* __restrict__ C,
    int M, int N, int K)
{
    __shared__ float As[128][36];
    __shared__ float Bs[32][136];

    const int tid  = threadIdx.x;
    const int wid  = tid >> 5;
    const int lane = tid & 31;
    const int g    = lane >> 2;
    const int tig  = lane & 3;
    const int warpM = wid & 3;    // 0..3
    const int warpN = wid >> 2;   // 0..1
    const int m0 = blockIdx.y * 128;
    const int n0 = blockIdx.x * 128;

    float acc[2][8][4];
#pragma unroll
    for (int mt = 0; mt < 2; mt++)
#pragma unroll
        for (int nt = 0; nt < 8; nt++)
#pragma unroll
            for (int i = 0; i < 4; i++) acc[mt][nt][i] = 0.f;

    for (int k0 = 0; k0 < K; k0 += 32) {
        // Stage A tile (128 x 32): 1024 16B segments
#pragma unroll
        for (int l = 0; l < 4; l++) {
            int idx = tid + l * 256;
            int m = idx >> 3, s = idx & 7;
            cp_async16(&As[m][s * 4], &A[(size_t)(m0 + m) * K + k0 + s * 4]);
        }
        // Stage B tile (32 x 128)
#pragma unroll
        for (int l = 0; l < 4; l++) {
            int idx = tid + l * 256;
            int kk = idx >> 5, s = idx & 31;
            cp_async16(&Bs[kk][s * 4], &B[(size_t)(k0 + kk) * N + n0 + s * 4]);
        }
        CP_COMMIT();
        CP_WAIT0();
        __syncthreads();

#pragma unroll
        for (int kk = 0; kk < 32; kk += 8) {
            unsigned af[2][4];
#pragma unroll
            for (int mt = 0; mt < 2; mt++) {
                int r = warpM * 32 + mt * 16 + g;
                af[mt][0] = cvt_tf32(As[r][kk + tig]);
                af[mt][1] = cvt_tf32(As[r + 8][kk + tig]);
                af[mt][2] = cvt_tf32(As[r][kk + tig + 4]);
                af[mt][3] = cvt_tf32(As[r + 8][kk + tig + 4]);
            }
            unsigned bf[8][2];
#pragma unroll
            for (int nt = 0; nt < 8; nt++) {
                int c = warpN * 64 + nt * 8 + g;
                bf[nt][0] = cvt_tf32(Bs[kk + tig][c]);
                bf[nt][1] = cvt_tf32(Bs[kk + tig + 4][c]);
            }
#pragma unroll
            for (int mt = 0; mt < 2; mt++)
#pragma unroll
                for (int nt = 0; nt < 8; nt++)
                    mma_tf32(acc[mt][nt], af[mt], bf[nt], acc[mt][nt]);
        }
        __syncthreads();
    }

    // Epilogue: bias (+ relu), float2 stores
#pragma unroll
    for (int mt = 0; mt < 2; mt++) {
        int r0 = m0 + warpM * 32 + mt * 16 + g;
#pragma unroll
        for (int nt = 0; nt < 8; nt++) {
            int c0 = n0 + warpN * 64 + nt * 8 + tig * 2;
            float b0 = bias[c0], b1 = bias[c0 + 1];
            float v0 = acc[mt][nt][0] + b0;
            float v1 = acc[mt][nt][1] + b1;
            float v2 = acc[mt][nt][2] + b0;
            float v3 = acc[mt][nt][3] + b1;
            if (RELU) {
                v0 = fmaxf(v0, 0.f); v1 = fmaxf(v1, 0.f);
                v2 = fmaxf(v2, 0.f); v3 = fmaxf(v3, 0.f);
            }
            *reinterpret_cast<float2*>(&C[(size_t)r0 * N + c0])       = make_float2(v0, v1);
            *reinterpret_cast<float2*>(&C[(size_t)(r0 + 8) * N + c0]) = make_float2(v2, v3);
        }
    }
}

// ----------------------------------------------------------------------------
// Attention scores (TF32 mma): S[bh,q,k] = (Q_bh . K_bh)*0.125 + mask*(-1e9)
// 128x128 score tile per block, head dim K=64 staged in two 32-chunks.
// mask_mode 0: causal (k > q -> masked, computed from indices)
// mask_mode 1: padding mask pmask[b*Skv + k]
// ----------------------------------------------------------------------------
__global__ __launch_bounds__(256, 2) void attn_scores_tf32(
    const float* __restrict__ Qf, const float* __restrict__ Kf,
    const float* __restrict__ pmask, int mask_mode,
    float* __restrict__ Sout, int Sq, int Skv)
{
    __shared__ float Qs[128][36];
    __shared__ float Ks[128][36];

    const int tid  = threadIdx.x;
    const int wid  = tid >> 5;
    const int lane = tid & 31;
    const int g    = lane >> 2;
    const int tig  = lane & 3;
    const int warpM = wid & 3;
    const int warpN = wid >> 2;
    const int bh = blockIdx.z;
    const int b = bh >> 4, h = bh & 15;
    const int q0 = blockIdx.y * 128;
    const int k0 = blockIdx.x * 128;

    float acc[2][8][4];
#pragma unroll
    for (int mt = 0; mt < 2; mt++)
#pragma unroll
        for (int nt = 0; nt < 8; nt++)
#pragma unroll
            for (int i = 0; i < 4; i++) acc[mt][nt][i] = 0.f;

#pragma unroll
    for (int d0 = 0; d0 < DHH; d0 += 32) {
#pragma unroll
        for (int l = 0; l < 4; l++) {
            int idx = tid + l * 256;
            int m = idx >> 3, s = idx & 7;
            cp_async16(&Qs[m][s * 4],
                       &Qf[(size_t)(b * Sq + q0 + m) * DD + h * DHH + d0 + s * 4]);
        }
#pragma unroll
        for (int l = 0; l < 4; l++) {
            int idx = tid + l * 256;
            int m = idx >> 3, s = idx & 7;
            cp_async16(&Ks[m][s * 4],
                       &Kf[(size_t)(b * Skv + k0 + m) * DD + h * DHH + d0 + s * 4]);
        }
        CP_COMMIT();
        CP_WAIT0();
        __syncthreads();

#pragma unroll
        for (int kk = 0; kk < 32; kk += 8) {
            unsigned af[2][4];
#pragma unroll
            for (int mt = 0; mt < 2; mt++) {
                int r = warpM * 32 + mt * 16 + g;
                af[mt][0] = cvt_tf32(Qs[r][kk + tig]);
                af[mt][1] = cvt_tf32(Qs[r + 8][kk + tig]);
                af[mt][2] = cvt_tf32(Qs[r][kk + tig + 4]);
                af[mt][3] = cvt_tf32(Qs[r + 8][kk + tig + 4]);
            }
            unsigned bf[8][2];
#pragma unroll
            for (int nt = 0; nt < 8; nt++) {
                int r = warpN * 64 + nt * 8 + g;   // key row
                bf[nt][0] = cvt_tf32(Ks[r][kk + tig]);
                bf[nt][1] = cvt_tf32(Ks[r][kk + tig + 4]);
            }
#pragma unroll
            for (int mt = 0; mt < 2; mt++)
#pragma unroll
                for (int nt = 0; nt < 8; nt++)
                    mma_tf32(acc[mt][nt], af[mt], bf[nt], acc[mt][nt]);
        }
        __syncthreads();
    }

    // Epilogue: scale + mask
#pragma unroll
    for (int mt = 0; mt < 2; mt++) {
        int qr0 = q0 + warpM * 32 + mt * 16 + g;
#pragma unroll
        for (int nt = 0; nt < 8; nt++) {
            int kc0 = k0 + warpN * 64 + nt * 8 + tig * 2;
#pragma unroll
            for (int half = 0; half < 2; half++) {
                int q = qr0 + half * 8;
                float v0 = acc[mt][nt][half * 2 + 0] * 0.125f;
                float v1 = acc[mt][nt][half * 2 + 1] * 0.125f;
                if (mask_mode == 0) {
                    if (kc0 > q)     v0 -= 1e9f;
                    if (kc0 + 1 > q) v1 -= 1e9f;
                } else {
                    v0 += pmask[(size_t)b * Skv + kc0] * (-1e9f);
                    v1 += pmask[(size_t)b * Skv + kc0 + 1] * (-1e9f);
                }
                *reinterpret_cast<float2*>(&Sout[((size_t)bh * Sq + q) * Skv + kc0]) =
                    make_float2(v0, v1);
            }
        }
    }
}

// ----------------------------------------------------------------------------
// Row softmax, ncols = 1024. One warp per row.
// ----------------------------------------------------------------------------
__global__ __launch_bounds__(256) void softmax_rows_kernel(
    float* __restrict__ P, int nrows)
{
    int row = blockIdx.x * 8 + threadIdx.y;
    if (row >= nrows) return;
    float* p = P + (size_t)row * 1024;
    const int lane = threadIdx.x;

    float v[32];
    float mx = -INFINITY;
#pragma unroll
    for (int i = 0; i < 32; i++) {
        v[i] = p[lane + i * 32];
        mx = fmaxf(mx, v[i]);
    }
#pragma unroll
    for (int o = 16; o; o >>= 1) mx = fmaxf(mx, __shfl_xor_sync(0xffffffffu, mx, o));

    float sum = 0.f;
#pragma unroll
    for (int i = 0; i < 32; i++) {
        v[i] = __expf(v[i] - mx);
        sum += v[i];
    }
#pragma unroll
    for (int o = 16; o; o >>= 1) sum += __shfl_xor_sync(0xffffffffu, sum, o);
    float inv = 1.f / sum;
#pragma unroll
    for (int i = 0; i < 32; i++) p[lane + i * 32] = v[i] * inv;
}

// ----------------------------------------------------------------------------
// attn_v (TF32 mma): ctx[b,q,h*64+d] = sum_k P[bh,q,k] * V[b,k,h*64+d]
// M=128(q) x N=64(d) tile per block, K=Skv in 32-chunks.
// 8 warps: 4m x 2n, warp tile 32x32 -> MT=2, NT=4.
// Vs stride 72 -> bank (8*k + n) % 32 distinct.
// ----------------------------------------------------------------------------
__global__ __launch_bounds__(256, 2) void attn_v_tf32(
    const float* __restrict__ P, const float* __restrict__ Vf,
    float* __restrict__ ctx, int Sq, int Skv)
{
    __shared__ float Ps[128][36];
    __shared__ float Vs[32][72];

    const int tid  = threadIdx.x;
    const int wid  = tid >> 5;
    const int lane = tid & 31;
    const int g    = lane >> 2;
    const int tig  = lane & 3;
    const int warpM = wid & 3;
    const int warpN = wid >> 2;
    const int bh = blockIdx.y;
    const int b = bh >> 4, h = bh & 15;
    const int q0 = blockIdx.x * 128;

    float acc[2][4][4];
#pragma unroll
    for (int mt = 0; mt < 2; mt++)
#pragma unroll
        for (int nt = 0; nt < 4; nt++)
#pragma unroll
            for (int i = 0; i < 4; i++) acc[mt][nt][i] = 0.f;

    for (int k0 = 0; k0 < Skv; k0 += 32) {
#pragma unroll
        for (int l = 0; l < 4; l++) {
            int idx = tid + l * 256;
            int m = idx >> 3, s = idx & 7;
            cp_async16(&Ps[m][s * 4],
                       &P[((size_t)bh * Sq + q0 + m) * Skv + k0 + s * 4]);
        }
#pragma unroll
        for (int l = 0; l < 2; l++) {
            int idx = tid + l * 256;           // 0..511
            int kk = idx >> 4, s = idx & 15;   // 32 rows x 16 segs
            cp_async16(&Vs[kk][s * 4],
                       &Vf[(size_t)(b * Skv + k0 + kk) * DD + h * DHH + s * 4]);
        }
        CP_COMMIT();
        CP_WAIT0();
        __syncthreads();

#pragma unroll
        for (int kk = 0; kk < 32; kk += 8) {
            unsigned af[2][4];
#pragma unroll
            for (int mt = 0; mt < 2; mt++) {
                int r = warpM * 32 + mt * 16 + g;
                af[mt][0] = cvt_tf32(Ps[r][kk + tig]);
                af[mt][1] = cvt_tf32(Ps[r + 8][kk + tig]);
                af[mt][2] = cvt_tf32(Ps[r][kk + tig + 4]);
                af[mt][3] = cvt_tf32(Ps[r + 8][kk + tig + 4]);
            }
            unsigned bf[4][2];
#pragma unroll
            for (int nt = 0; nt < 4; nt++) {
                int c = warpN * 32 + nt * 8 + g;
                bf[nt][0] = cvt_tf32(Vs[kk + tig][c]);
                bf[nt][1] = cvt_tf32(Vs[kk + tig + 4][c]);
            }
#pragma unroll
            for (int mt = 0; mt < 2; mt++)
#pragma unroll
                for (int nt = 0; nt < 4; nt++)
                    mma_tf32(acc[mt][nt], af[mt], bf[nt], acc[mt][nt]);
        }
        __syncthreads();
    }

#pragma unroll
    for (int mt = 0; mt < 2; mt++) {
        int qr0 = q0 + warpM * 32 + mt * 16 + g;
#pragma unroll
        for (int nt = 0; nt < 4; nt++) {
            int c0 = warpN * 32 + nt * 8 + tig * 2;
            *reinterpret_cast<float2*>(
                &ctx[(size_t)(b * Sq + qr0) * DD + h * DHH + c0]) =
                make_float2(acc[mt][nt][0], acc[mt][nt][1]);
            *reinterpret_cast<float2*>(
                &ctx[(size_t)(b * Sq + qr0 + 8) * DD + h * DHH + c0]) =
                make_float2(acc[mt][nt][2], acc[mt][nt][3]);
        }
    }
}

// ----------------------------------------------------------------------------
// out[row,:] = LayerNorm(a[row,:] + b[row,:]) * g + beta   (D = 1024)
// ----------------------------------------------------------------------------
__global__ __launch_bounds__(256) void add_ln_kernel(
    const float* __restrict__ a, const float* __restrict__ b,
    const float* __restrict__ g, const float* __restrict__ be,
    float* __restrict__ o)
{
    const int row = blockIdx.x;
    const int tid = threadIdx.x;
    const float* pa = a + (size_t)row * DD;
    const float* pb = b + (size_t)row * DD;

    __shared__ float red[8];
    float v[4];
    float s = 0.f;
#pragma unroll
    for (int i = 0; i < 4; i++) {
        int c = tid + i * 256;
        v[i] = pa[c] + pb[c];
        s += v[i];
    }
#pragma unroll
    for (int o2 = 16; o2; o2 >>= 1) s += __shfl_xor_sync(0xffffffffu, s, o2);
    if ((tid & 31) == 0) red[tid >> 5] = s;
    __syncthreads();
    if (tid < 32) {
        float t = (tid < 8) ? red[tid] : 0.f;
#pragma unroll
        for (int o2 = 4; o2; o2 >>= 1) t += __shfl_xor_sync(0xffffffffu, t, o2);
        if (tid == 0) red[0] = t;
    }
    __syncthreads();
    const float mu = red[0] * (1.f / 1024.f);
    __syncthreads();

    float s2 = 0.f;
#pragma unroll
    for (int i = 0; i < 4; i++) {
        float d = v[i] - mu;
        s2 += d * d;
    }
#pragma unroll
    for (int o2 = 16; o2; o2 >>= 1) s2 += __shfl_xor_sync(0xffffffffu, s2, o2);
    if ((tid & 31) == 0) red[tid >> 5] = s2;
    __syncthreads();
    if (tid < 32) {
        float t = (tid < 8) ? red[tid] : 0.f;
#pragma unroll
        for (int o2 = 4; o2; o2 >>= 1) t += __shfl_xor_sync(0xffffffffu, t, o2);
        if (tid == 0) red[0] = t;
    }
    __syncthreads();
    const float rstd = rsqrtf(red[0] * (1.f / 1024.f) + LN_EPS);

#pragma unroll
    for (int i = 0; i < 4; i++) {
        int c = tid + i * 256;
        o[(size_t)row * DD + c] = (v[i] - mu) * rstd * g[c] + be[c];
    }
}

// ----------------------------------------------------------------------------
// Host launch
// ----------------------------------------------------------------------------
static void launch_gemm(const float* A, const float* B, const float* bias,
                        float* C, int M, int N, int K, bool relu)
{
    dim3 grid(N / 128, M / 128);
    if (relu)
        gemm_tf32_kernel<1><<<grid, 256>>>(A, B, bias, C, M, N, K);
    else
        gemm_tf32_kernel<0><<<grid, 256>>>(A, B, bias, C, M, N, K);
}

extern "C" void kernel_launch(void* const* d_in, const int* in_sizes, int n_in,
                              void* d_out, int out_size)
{
    const float* x      = (const float*)d_in[0];
    const float* enc    = (const float*)d_in[1];
    const float* causal = (const float*)d_in[2];
    const float* pmask  = (const float*)d_in[3];
    (void)causal;

    const float* m1_wq = (const float*)d_in[4];
    const float* m1_qb = (const float*)d_in[5];
    const float* m1_wk = (const float*)d_in[6];
    const float* m1_kb = (const float*)d_in[7];
    const float* m1_wv = (const float*)d_in[8];
    const float* m1_vb = (const float*)d_in[9];
    const float* m1_wo = (const float*)d_in[10];
    const float* m1_ob = (const float*)d_in[11];

    const float* m2_wq = (const float*)d_in[12];
    const float* m2_qb = (const float*)d_in[13];
    const float* m2_wk = (const float*)d_in[14];
    const float* m2_kb = (const float*)d_in[15];
    const float* m2_wv = (const float*)d_in[16];
    const float* m2_vb = (const float*)d_in[17];
    const float* m2_wo = (const float*)d_in[18];
    const float* m2_ob = (const float*)d_in[19];

    const float* ffn_w1 = (const float*)d_in[20];
    const float* ffn_b1 = (const float*)d_in[21];
    const float* ffn_w2 = (const float*)d_in[22];
    const float* ffn_b2 = (const float*)d_in[23];

    const float* ln1_g = (const float*)d_in[24];
    const float* ln1_b = (const float*)d_in[25];
    const float* ln2_g = (const float*)d_in[26];
    const float* ln2_b = (const float*)d_in[27];
    const float* ln3_g = (const float*)d_in[28];
    const float* ln3_b = (const float*)d_in[29];

    float* out = (float*)d_out;

    float *q, *k, *v, *ctx, *t0, *x1, *y, *ffn, *scores;
    cudaGetSymbolAddress((void**)&q,      g_q);
    cudaGetSymbolAddress((void**)&k,      g_k);
    cudaGetSymbolAddress((void**)&v,      g_v);
    cudaGetSymbolAddress((void**)&ctx,    g_ctx);
    cudaGetSymbolAddress((void**)&t0,     g_t0);
    cudaGetSymbolAddress((void**)&x1,     g_x1);
    cudaGetSymbolAddress((void**)&y,      g_y);
    cudaGetSymbolAddress((void**)&ffn,    g_ffn);
    cudaGetSymbolAddress((void**)&scores, g_scores);

    const size_t OUTN = (size_t)BB * SS * DD;
    const size_t ATT  = (size_t)BB * HH * SS * SS;
    float* attn1 = ((size_t)out_size >= OUTN + ATT)     ? out + OUTN       : scores;
    float* attn2 = ((size_t)out_size >= OUTN + 2 * ATT) ? out + OUTN + ATT : scores;

    const int BS = BB * SS;
    const int BE = BB * EE;
    const int nrowsAttn = BB * HH * SS;

    // ---------------- MHA1 (masked self-attention) ----------------
    launch_gemm(x, m1_wq, m1_qb, q, BS, DD, DD, false);
    launch_gemm(x, m1_wk, m1_kb, k, BS, DD, DD, false);
    launch_gemm(x, m1_wv, m1_vb, v, BS, DD, DD, false);

    attn_scores_tf32<<<dim3(SS / 128, SS / 128, BB * HH), 256>>>(
        q, k, pmask, /*mask_mode=*/0, attn1, SS, SS);
    softmax_rows_kernel<<<nrowsAttn / 8, dim3(32, 8)>>>(attn1, nrowsAttn);
    attn_v_tf32<<<dim3(SS / 128, BB * HH), 256>>>(attn1, v, ctx, SS, SS);

    launch_gemm(ctx, m1_wo, m1_ob, t0, BS, DD, DD, false);
    add_ln_kernel<<<BS, 256>>>(x, t0, ln1_g, ln1_b, x1);

    // ---------------- MHA2 (cross-attention) ----------------
    launch_gemm(x1,  m2_wq, m2_qb, q, BS, DD, DD, false);
    launch_gemm(enc, m2_wk, m2_kb, k, BE, DD, DD, false);
    launch_gemm(enc, m2_wv, m2_vb, v, BE, DD, DD, false);

    attn_scores_tf32<<<dim3(EE / 128, SS / 128, BB * HH), 256>>>(
        q, k, pmask, /*mask_mode=*/1, attn2, SS, EE);
    softmax_rows_kernel<<<nrowsAttn / 8, dim3(32, 8)>>>(attn2, nrowsAttn);
    attn_v_tf32<<<dim3(SS / 128, BB * HH), 256>>>(attn2, v, ctx, SS, EE);

    launch_gemm(ctx, m2_wo, m2_ob, t0, BS, DD, DD, false);
    add_ln_kernel<<<BS, 256>>>(t0, x1, ln2_g, ln2_b, y);

    // ---------------- FFN ----------------
    launch_gemm(y, ffn_w1, ffn_b1, ffn, BS, DFF, DD, true);
    launch_gemm(ffn, ffn_w2, ffn_b2, t0, BS, DD, DFF, false);
    add_ln_kernel<<<BS, 256>>>(y, t0, ln3_g, ln3_b, out);
}

// round 5
// speedup vs baseline: 3.3705x; 1.1557x over previous
#include <cuda_runtime.h>
#include <cuda_bf16.h>
#include <math.h>

// Problem constants
#define BB 4
#define SS 1024
#define EE 1024
#define DD 1024
#define HH 16
#define DHH 64
#define DFF 4096
#define LN_EPS 1e-6f

// ----------------------------------------------------------------------------
// Scratch (static device globals; no allocations allowed)
// ----------------------------------------------------------------------------
__device__ float g_q   [BB * SS * DD];
__device__ float g_k   [BB * EE * DD];
__device__ float g_v   [BB * EE * DD];
__device__ float g_ctx [BB * SS * DD];
__device__ float g_t0  [BB * SS * DD];
__device__ float g_x1  [BB * SS * DD];
__device__ float g_y   [BB * SS * DD];
__device__ float g_ffn [BB * SS * DFF];
__device__ float g_scores[(size_t)BB * HH * SS * SS];

// ----------------------------------------------------------------------------
// TF32 mma helpers
// ----------------------------------------------------------------------------
__device__ __forceinline__ unsigned cvt_tf32(float x) {
    unsigned r;
    asm("cvt.rna.tf32.f32 %0, %1;" : "=r"(r) : "f"(x));
    return r;
}

__device__ __forceinline__ void mma_tf32(float* d, const unsigned* a,
                                         const unsigned* b, const float* c) {
    asm("mma.sync.aligned.m16n8k8.row.col.f32.tf32.tf32.f32 "
        "{%0,%1,%2,%3}, {%4,%5,%6,%7}, {%8,%9}, {%10,%11,%12,%13};"
        : "=f"(d[0]), "=f"(d[1]), "=f"(d[2]), "=f"(d[3])
        : "r"(a[0]), "r"(a[1]), "r"(a[2]), "r"(a[3]),
          "r"(b[0]), "r"(b[1]),
          "f"(c[0]), "f"(c[1]), "f"(c[2]), "f"(c[3]));
}

__device__ __forceinline__ void cp_async16(void* smem, const void* gmem) {
    unsigned saddr = (unsigned)__cvta_generic_to_shared(smem);
    asm volatile("cp.async.cg.shared.global [%0], [%1], 16;" :: "r"(saddr), "l"(gmem));
}
#define CP_COMMIT() asm volatile("cp.async.commit_group;")
__device__ __forceinline__ void cp_wait0() { asm volatile("cp.async.wait_group 0;"); }
__device__ __forceinline__ void cp_wait1() { asm volatile("cp.async.wait_group 1;"); }

// ----------------------------------------------------------------------------
// TF32 GEMM, 2-stage cp.async pipeline.
// C[M,N] = A[M,K] @ B[K,N] + bias[N], optional ReLU.
// 128x128x32 CTA tile, 8 warps (4m x 2n), warp tile 32x64.
// Dynamic smem: 2 stages of As[128][36] + Bs[32][136]  (71680 B).
// ----------------------------------------------------------------------------
#define GEMM_SMEM (2 * (128 * 36 + 32 * 136) * 4)
#define AS_OFF(st) ((st) * 128 * 36)
#define BS_OFF(st) (2 * 128 * 36 + (st) * 32 * 136)

template <int RELU>
__global__ __launch_bounds__(256, 2) void gemm_tf32_kernel(
    const float* __restrict__ A, const float* __restrict__ B,
    const float* __restrict__ bias, float* __restrict__ C,
    int M, int N, int K)
{
    extern __shared__ float sm[];

    const int tid  = threadIdx.x;
    const int wid  = tid >> 5;
    const int lane = tid & 31;
    const int g    = lane >> 2;
    const int tig  = lane & 3;
    const int warpM = wid & 3;
    const int warpN = wid >> 2;
    const int m0 = blockIdx.y * 128;
    const int n0 = blockIdx.x * 128;

    float acc[2][8][4];
#pragma unroll
    for (int mt = 0; mt < 2; mt++)
#pragma unroll
        for (int nt = 0; nt < 8; nt++)
#pragma unroll
            for (int i = 0; i < 4; i++) acc[mt][nt][i] = 0.f;

    auto load_stage = [&](int st, int k0) {
        float* As = sm + AS_OFF(st);
        float* Bs = sm + BS_OFF(st);
#pragma unroll
        for (int l = 0; l < 4; l++) {
            int idx = tid + l * 256;
            int m = idx >> 3, s = idx & 7;
            cp_async16(&As[m * 36 + s * 4], &A[(size_t)(m0 + m) * K + k0 + s * 4]);
        }
#pragma unroll
        for (int l = 0; l < 4; l++) {
            int idx = tid + l * 256;
            int kk = idx >> 5, s = idx & 31;
            cp_async16(&Bs[kk * 136 + s * 4], &B[(size_t)(k0 + kk) * N + n0 + s * 4]);
        }
        CP_COMMIT();
    };

    const int T = K >> 5;
    load_stage(0, 0);

    for (int t = 0; t < T; t++) {
        if (t + 1 < T) { load_stage((t + 1) & 1, (t + 1) << 5); cp_wait1(); }
        else           { cp_wait0(); }
        __syncthreads();

        const float* As = sm + AS_OFF(t & 1);
        const float* Bs = sm + BS_OFF(t & 1);
#pragma unroll
        for (int kk = 0; kk < 32; kk += 8) {
            unsigned af[2][4];
#pragma unroll
            for (int mt = 0; mt < 2; mt++) {
                int r = warpM * 32 + mt * 16 + g;
                af[mt][0] = cvt_tf32(As[r * 36 + kk + tig]);
                af[mt][1] = cvt_tf32(As[(r + 8) * 36 + kk + tig]);
                af[mt][2] = cvt_tf32(As[r * 36 + kk + tig + 4]);
                af[mt][3] = cvt_tf32(As[(r + 8) * 36 + kk + tig + 4]);
            }
            unsigned bf[8][2];
#pragma unroll
            for (int nt = 0; nt < 8; nt++) {
                int c = warpN * 64 + nt * 8 + g;
                bf[nt][0] = cvt_tf32(Bs[(kk + tig) * 136 + c]);
                bf[nt][1] = cvt_tf32(Bs[(kk + tig + 4) * 136 + c]);
            }
#pragma unroll
            for (int mt = 0; mt < 2; mt++)
#pragma unroll
                for (int nt = 0; nt < 8; nt++)
                    mma_tf32(acc[mt][nt], af[mt], bf[nt], acc[mt][nt]);
        }
        __syncthreads();
    }

#pragma unroll
    for (int mt = 0; mt < 2; mt++) {
        int r0 = m0 + warpM * 32 + mt * 16 + g;
#pragma unroll
        for (int nt = 0; nt < 8; nt++) {
            int c0 = n0 + warpN * 64 + nt * 8 + tig * 2;
            float b0 = bias[c0], b1 = bias[c0 + 1];
            float v0 = acc[mt][nt][0] + b0;
            float v1 = acc[mt][nt][1] + b1;
            float v2 = acc[mt][nt][2] + b0;
            float v3 = acc[mt][nt][3] + b1;
            if (RELU) {
                v0 = fmaxf(v0, 0.f); v1 = fmaxf(v1, 0.f);
                v2 = fmaxf(v2, 0.f); v3 = fmaxf(v3, 0.f);
            }
            *reinterpret_cast<float2*>(&C[(size_t)r0 * N + c0])       = make_float2(v0, v1);
            *reinterpret_cast<float2*>(&C[(size_t)(r0 + 8) * N + c0]) = make_float2(v2, v3);
        }
    }
}

// ----------------------------------------------------------------------------
// Attention scores (TF32 mma): S[bh,q,k] = (Q . K)*0.125 + mask*(-1e9)
// Full head dim (64) staged in one shot: Qs[128][68], Ks[128][68] (69632 B).
// Causal fully-masked tiles (k0 > q0+127) short-circuit to a -1e9 fill.
// ----------------------------------------------------------------------------
#define SCORES_SMEM (2 * 128 * 68 * 4)

__global__ __launch_bounds__(256, 2) void attn_scores_tf32(
    const float* __restrict__ Qf, const float* __restrict__ Kf,
    const float* __restrict__ pmask, int mask_mode,
    float* __restrict__ Sout, int Sq, int Skv)
{
    extern __shared__ float sm[];
    float* Qs = sm;                 // [128][68]
    float* Ks = sm + 128 * 68;

    const int tid  = threadIdx.x;
    const int wid  = tid >> 5;
    const int lane = tid & 31;
    const int g    = lane >> 2;
    const int tig  = lane & 3;
    const int warpM = wid & 3;
    const int warpN = wid >> 2;
    const int bh = blockIdx.z;
    const int b = bh >> 4, h = bh & 15;
    const int q0 = blockIdx.y * 128;
    const int k0 = blockIdx.x * 128;

    // Fully-masked causal tile: fill and exit (no loads, no mma).
    if (mask_mode == 0 && k0 > q0 + 127) {
#pragma unroll
        for (int mt = 0; mt < 2; mt++) {
            int qr0 = q0 + warpM * 32 + mt * 16 + g;
#pragma unroll
            for (int nt = 0; nt < 8; nt++) {
                int kc0 = k0 + warpN * 64 + nt * 8 + tig * 2;
#pragma unroll
                for (int half = 0; half < 2; half++) {
                    int q = qr0 + half * 8;
                    *reinterpret_cast<float2*>(&Sout[((size_t)bh * Sq + q) * Skv + kc0]) =
                        make_float2(-1e9f, -1e9f);
                }
            }
        }
        return;
    }

    // Stage Q and K tiles (128 x 64 each)
#pragma unroll
    for (int l = 0; l < 8; l++) {
        int idx = tid + l * 256;        // 0..2047
        int m = idx >> 4, s = idx & 15;
        cp_async16(&Qs[m * 68 + s * 4],
                   &Qf[(size_t)(b * Sq + q0 + m) * DD + h * DHH + s * 4]);
    }
#pragma unroll
    for (int l = 0; l < 8; l++) {
        int idx = tid + l * 256;
        int m = idx >> 4, s = idx & 15;
        cp_async16(&Ks[m * 68 + s * 4],
                   &Kf[(size_t)(b * Skv + k0 + m) * DD + h * DHH + s * 4]);
    }
    CP_COMMIT();
    cp_wait0();
    __syncthreads();

    float acc[2][8][4];
#pragma unroll
    for (int mt = 0; mt < 2; mt++)
#pragma unroll
        for (int nt = 0; nt < 8; nt++)
#pragma unroll
            for (int i = 0; i < 4; i++) acc[mt][nt][i] = 0.f;

#pragma unroll
    for (int kk = 0; kk < 64; kk += 8) {
        unsigned af[2][4];
#pragma unroll
        for (int mt = 0; mt < 2; mt++) {
            int r = warpM * 32 + mt * 16 + g;
            af[mt][0] = cvt_tf32(Qs[r * 68 + kk + tig]);
            af[mt][1] = cvt_tf32(Qs[(r + 8) * 68 + kk + tig]);
            af[mt][2] = cvt_tf32(Qs[r * 68 + kk + tig + 4]);
            af[mt][3] = cvt_tf32(Qs[(r + 8) * 68 + kk + tig + 4]);
        }
        unsigned bf[8][2];
#pragma unroll
        for (int nt = 0; nt < 8; nt++) {
            int r = warpN * 64 + nt * 8 + g;
            bf[nt][0] = cvt_tf32(Ks[r * 68 + kk + tig]);
            bf[nt][1] = cvt_tf32(Ks[r * 68 + kk + tig + 4]);
        }
#pragma unroll
        for (int mt = 0; mt < 2; mt++)
#pragma unroll
            for (int nt = 0; nt < 8; nt++)
                mma_tf32(acc[mt][nt], af[mt], bf[nt], acc[mt][nt]);
    }

#pragma unroll
    for (int mt = 0; mt < 2; mt++) {
        int qr0 = q0 + warpM * 32 + mt * 16 + g;
#pragma unroll
        for (int nt = 0; nt < 8; nt++) {
            int kc0 = k0 + warpN * 64 + nt * 8 + tig * 2;
#pragma unroll
            for (int half = 0; half < 2; half++) {
                int q = qr0 + half * 8;
                float v0 = acc[mt][nt][half * 2 + 0] * 0.125f;
                float v1 = acc[mt][nt][half * 2 + 1] * 0.125f;
                if (mask_mode == 0) {
                    if (kc0 > q)     v0 -= 1e9f;
                    if (kc0 + 1 > q) v1 -= 1e9f;
                } else {
                    v0 += pmask[(size_t)b * Skv + kc0] * (-1e9f);
                    v1 += pmask[(size_t)b * Skv + kc0 + 1] * (-1e9f);
                }
                *reinterpret_cast<float2*>(&Sout[((size_t)bh * Sq + q) * Skv + kc0]) =
                    make_float2(v0, v1);
            }
        }
    }
}

// ----------------------------------------------------------------------------
// Row softmax, ncols = 1024. One warp per row.
// ----------------------------------------------------------------------------
__global__ __launch_bounds__(256) void softmax_rows_kernel(
    float* __restrict__ P, int nrows)
{
    int row = blockIdx.x * 8 + threadIdx.y;
    if (row >= nrows) return;
    float* p = P + (size_t)row * 1024;
    const int lane = threadIdx.x;

    float v[32];
    float mx = -INFINITY;
#pragma unroll
    for (int i = 0; i < 32; i++) {
        v[i] = p[lane + i * 32];
        mx = fmaxf(mx, v[i]);
    }
#pragma unroll
    for (int o = 16; o; o >>= 1) mx = fmaxf(mx, __shfl_xor_sync(0xffffffffu, mx, o));

    float sum = 0.f;
#pragma unroll
    for (int i = 0; i < 32; i++) {
        v[i] = __expf(v[i] - mx);
        sum += v[i];
    }
#pragma unroll
    for (int o = 16; o; o >>= 1) sum += __shfl_xor_sync(0xffffffffu, sum, o);
    float inv = 1.f / sum;
#pragma unroll
    for (int i = 0; i < 32; i++) p[lane + i * 32] = v[i] * inv;
}

// ----------------------------------------------------------------------------
// attn_v (TF32 mma, 2-stage pipeline): ctx = P @ V  (per (b,h))
// M=128(q) x N=64(d), K loop over Skv in 32-chunks (truncated for causal).
// Dynamic smem: 2 stages of Ps[128][36] + Vs[32][72]  (55296 B).
// ----------------------------------------------------------------------------
#define ATTNV_SMEM (2 * (128 * 36 + 32 * 72) * 4)
#define PS_OFF(st) ((st) * 128 * 36)
#define VS_OFF(st) (2 * 128 * 36 + (st) * 32 * 72)

__global__ __launch_bounds__(256, 2) void attn_v_tf32(
    const float* __restrict__ P, const float* __restrict__ Vf,
    float* __restrict__ ctx, int Sq, int Skv, int mask_mode)
{
    extern __shared__ float sm[];

    const int tid  = threadIdx.x;
    const int wid  = tid >> 5;
    const int lane = tid & 31;
    const int g    = lane >> 2;
    const int tig  = lane & 3;
    const int warpM = wid & 3;
    const int warpN = wid >> 2;
    const int bh = blockIdx.y;
    const int b = bh >> 4, h = bh & 15;
    const int q0 = blockIdx.x * 128;

    // Causal: P[q,k] == 0 exactly for k > q, so stop at q0+128.
    const int kEnd = (mask_mode == 0) ? min(Skv, q0 + 128) : Skv;
    const int T = kEnd >> 5;

    float acc[2][4][4];
#pragma unroll
    for (int mt = 0; mt < 2; mt++)
#pragma unroll
        for (int nt = 0; nt < 4; nt++)
#pragma unroll
            for (int i = 0; i < 4; i++) acc[mt][nt][i] = 0.f;

    auto load_stage = [&](int st, int k0) {
        float* Ps = sm + PS_OFF(st);
        float* Vs = sm + VS_OFF(st);
#pragma unroll
        for (int l = 0; l < 4; l++) {
            int idx = tid + l * 256;
            int m = idx >> 3, s = idx & 7;
            cp_async16(&Ps[m * 36 + s * 4],
                       &P[((size_t)bh * Sq + q0 + m) * Skv + k0 + s * 4]);
        }
#pragma unroll
        for (int l = 0; l < 2; l++) {
            int idx = tid + l * 256;
            int kk = idx >> 4, s = idx & 15;
            cp_async16(&Vs[kk * 72 + s * 4],
                       &Vf[(size_t)(b * Skv + k0 + kk) * DD + h * DHH + s * 4]);
        }
        CP_COMMIT();
    };

    load_stage(0, 0);

    for (int t = 0; t < T; t++) {
        if (t + 1 < T) { load_stage((t + 1) & 1, (t + 1) << 5); cp_wait1(); }
        else           { cp_wait0(); }
        __syncthreads();

        const float* Ps = sm + PS_OFF(t & 1);
        const float* Vs = sm + VS_OFF(t & 1);
#pragma unroll
        for (int kk = 0; kk < 32; kk += 8) {
            unsigned af[2][4];
#pragma unroll
            for (int mt = 0; mt < 2; mt++) {
                int r = warpM * 32 + mt * 16 + g;
                af[mt][0] = cvt_tf32(Ps[r * 36 + kk + tig]);
                af[mt][1] = cvt_tf32(Ps[(r + 8) * 36 + kk + tig]);
                af[mt][2] = cvt_tf32(Ps[r * 36 + kk + tig + 4]);
                af[mt][3] = cvt_tf32(Ps[(r + 8) * 36 + kk + tig + 4]);
            }
            unsigned bf[4][2];
#pragma unroll
            for (int nt = 0; nt < 4; nt++) {
                int c = warpN * 32 + nt * 8 + g;
                bf[nt][0] = cvt_tf32(Vs[(kk + tig) * 72 + c]);
                bf[nt][1] = cvt_tf32(Vs[(kk + tig + 4) * 72 + c]);
            }
#pragma unroll
            for (int mt = 0; mt < 2; mt++)
#pragma unroll
                for (int nt = 0; nt < 4; nt++)
                    mma_tf32(acc[mt][nt], af[mt], bf[nt], acc[mt][nt]);
        }
        __syncthreads();
    }

#pragma unroll
    for (int mt = 0; mt < 2; mt++) {
        int qr0 = q0 + warpM * 32 + mt * 16 + g;
#pragma unroll
        for (int nt = 0; nt < 4; nt++) {
            int c0 = warpN * 32 + nt * 8 + tig * 2;
            *reinterpret_cast<float2*>(
                &ctx[(size_t)(b * Sq + qr0) * DD + h * DHH + c0]) =
                make_float2(acc[mt][nt][0], acc[mt][nt][1]);
            *reinterpret_cast<float2*>(
                &ctx[(size_t)(b * Sq + qr0 + 8) * DD + h * DHH + c0]) =
                make_float2(acc[mt][nt][2], acc[mt][nt][3]);
        }
    }
}

// ----------------------------------------------------------------------------
// out[row,:] = LayerNorm(a[row,:] + b[row,:]) * g + beta   (D = 1024)
// ----------------------------------------------------------------------------
__global__ __launch_bounds__(256) void add_ln_kernel(
    const float* __restrict__ a, const float* __restrict__ b,
    const float* __restrict__ g, const float* __restrict__ be,
    float* __restrict__ o)
{
    const int row = blockIdx.x;
    const int tid = threadIdx.x;
    const float* pa = a + (size_t)row * DD;
    const float* pb = b + (size_t)row * DD;

    __shared__ float red[8];
    float v[4];
    float s = 0.f;
#pragma unroll
    for (int i = 0; i < 4; i++) {
        int c = tid + i * 256;
        v[i] = pa[c] + pb[c];
        s += v[i];
    }
#pragma unroll
    for (int o2 = 16; o2; o2 >>= 1) s += __shfl_xor_sync(0xffffffffu, s, o2);
    if ((tid & 31) == 0) red[tid >> 5] = s;
    __syncthreads();
    if (tid < 32) {
        float t = (tid < 8) ? red[tid] : 0.f;
#pragma unroll
        for (int o2 = 4; o2; o2 >>= 1) t += __shfl_xor_sync(0xffffffffu, t, o2);
        if (tid == 0) red[0] = t;
    }
    __syncthreads();
    const float mu = red[0] * (1.f / 1024.f);
    __syncthreads();

    float s2 = 0.f;
#pragma unroll
    for (int i = 0; i < 4; i++) {
        float d = v[i] - mu;
        s2 += d * d;
    }
#pragma unroll
    for (int o2 = 16; o2; o2 >>= 1) s2 += __shfl_xor_sync(0xffffffffu, s2, o2);
    if ((tid & 31) == 0) red[tid >> 5] = s2;
    __syncthreads();
    if (tid < 32) {
        float t = (tid < 8) ? red[tid] : 0.f;
#pragma unroll
        for (int o2 = 4; o2; o2 >>= 1) t += __shfl_xor_sync(0xffffffffu, t, o2);
        if (tid == 0) red[0] = t;
    }
    __syncthreads();
    const float rstd = rsqrtf(red[0] * (1.f / 1024.f) + LN_EPS);

#pragma unroll
    for (int i = 0; i < 4; i++) {
        int c = tid + i * 256;
        o[(size_t)row * DD + c] = (v[i] - mu) * rstd * g[c] + be[c];
    }
}

// ----------------------------------------------------------------------------
// Host launch
// ----------------------------------------------------------------------------
static void launch_gemm(const float* A, const float* B, const float* bias,
                        float* C, int M, int N, int K, bool relu)
{
    dim3 grid(N / 128, M / 128);
    if (relu)
        gemm_tf32_kernel<1><<<grid, 256, GEMM_SMEM>>>(A, B, bias, C, M, N, K);
    else
        gemm_tf32_kernel<0><<<grid, 256, GEMM_SMEM>>>(A, B, bias, C, M, N, K);
}

extern "C" void kernel_launch(void* const* d_in, const int* in_sizes, int n_in,
                              void* d_out, int out_size)
{
    // One-time (idempotent) dynamic-smem opt-ins; host-side, capture-safe.
    cudaFuncSetAttribute(gemm_tf32_kernel<0>,
                         cudaFuncAttributeMaxDynamicSharedMemorySize, GEMM_SMEM);
    cudaFuncSetAttribute(gemm_tf32_kernel<1>,
                         cudaFuncAttributeMaxDynamicSharedMemorySize, GEMM_SMEM);
    cudaFuncSetAttribute(attn_scores_tf32,
                         cudaFuncAttributeMaxDynamicSharedMemorySize, SCORES_SMEM);
    cudaFuncSetAttribute(attn_v_tf32,
                         cudaFuncAttributeMaxDynamicSharedMemorySize, ATTNV_SMEM);

    const float* x      = (const float*)d_in[0];
    const float* enc    = (const float*)d_in[1];
    const float* causal = (const float*)d_in[2];
    const float* pmask  = (const float*)d_in[3];
    (void)causal;

    const float* m1_wq = (const float*)d_in[4];
    const float* m1_qb = (const float*)d_in[5];
    const float* m1_wk = (const float*)d_in[6];
    const float* m1_kb = (const float*)d_in[7];
    const float* m1_wv = (const float*)d_in[8];
    const float* m1_vb = (const float*)d_in[9];
    const float* m1_wo = (const float*)d_in[10];
    const float* m1_ob = (const float*)d_in[11];

    const float* m2_wq = (const float*)d_in[12];
    const float* m2_qb = (const float*)d_in[13];
    const float* m2_wk = (const float*)d_in[14];
    const float* m2_kb = (const float*)d_in[15];
    const float* m2_wv = (const float*)d_in[16];
    const float* m2_vb = (const float*)d_in[17];
    const float* m2_wo = (const float*)d_in[18];
    const float* m2_ob = (const float*)d_in[19];

    const float* ffn_w1 = (const float*)d_in[20];
    const float* ffn_b1 = (const float*)d_in[21];
    const float* ffn_w2 = (const float*)d_in[22];
    const float* ffn_b2 = (const float*)d_in[23];

    const float* ln1_g = (const float*)d_in[24];
    const float* ln1_b = (const float*)d_in[25];
    const float* ln2_g = (const float*)d_in[26];
    const float* ln2_b = (const float*)d_in[27];
    const float* ln3_g = (const float*)d_in[28];
    const float* ln3_b = (const float*)d_in[29];

    float* out = (float*)d_out;

    float *q, *k, *v, *ctx, *t0, *x1, *y, *ffn, *scores;
    cudaGetSymbolAddress((void**)&q,      g_q);
    cudaGetSymbolAddress((void**)&k,      g_k);
    cudaGetSymbolAddress((void**)&v,      g_v);
    cudaGetSymbolAddress((void**)&ctx,    g_ctx);
    cudaGetSymbolAddress((void**)&t0,     g_t0);
    cudaGetSymbolAddress((void**)&x1,     g_x1);
    cudaGetSymbolAddress((void**)&y,      g_y);
    cudaGetSymbolAddress((void**)&ffn,    g_ffn);
    cudaGetSymbolAddress((void**)&scores, g_scores);

    const size_t OUTN = (size_t)BB * SS * DD;
    const size_t ATT  = (size_t)BB * HH * SS * SS;
    float* attn1 = ((size_t)out_size >= OUTN + ATT)     ? out + OUTN       : scores;
    float* attn2 = ((size_t)out_size >= OUTN + 2 * ATT) ? out + OUTN + ATT : scores;

    const int BS = BB * SS;
    const int BE = BB * EE;
    const int nrowsAttn = BB * HH * SS;

    // ---------------- MHA1 (masked self-attention) ----------------
    launch_gemm(x, m1_wq, m1_qb, q, BS, DD, DD, false);
    launch_gemm(x, m1_wk, m1_kb, k, BS, DD, DD, false);
    launch_gemm(x, m1_wv, m1_vb, v, BS, DD, DD, false);

    attn_scores_tf32<<<dim3(SS / 128, SS / 128, BB * HH), 256, SCORES_SMEM>>>(
        q, k, pmask, /*mask_mode=*/0, attn1, SS, SS);
    softmax_rows_kernel<<<nrowsAttn / 8, dim3(32, 8)>>>(attn1, nrowsAttn);
    attn_v_tf32<<<dim3(SS / 128, BB * HH), 256, ATTNV_SMEM>>>(
        attn1, v, ctx, SS, SS, /*mask_mode=*/0);

    launch_gemm(ctx, m1_wo, m1_ob, t0, BS, DD, DD, false);
    add_ln_kernel<<<BS, 256>>>(x, t0, ln1_g, ln1_b, x1);

    // ---------------- MHA2 (cross-attention) ----------------
    launch_gemm(x1,  m2_wq, m2_qb, q, BS, DD, DD, false);
    launch_gemm(enc, m2_wk, m2_kb, k, BE, DD, DD, false);
    launch_gemm(enc, m2_wv, m2_vb, v, BE, DD, DD, false);

    attn_scores_tf32<<<dim3(EE / 128, SS / 128, BB * HH), 256, SCORES_SMEM>>>(
        q, k, pmask, /*mask_mode=*/1, attn2, SS, EE);
    softmax_rows_kernel<<<nrowsAttn / 8, dim3(32, 8)>>>(attn2, nrowsAttn);
    attn_v_tf32<<<dim3(SS / 128, BB * HH), 256, ATTNV_SMEM>>>(
        attn2, v, ctx, SS, EE, /*mask_mode=*/1);

    launch_gemm(ctx, m2_wo, m2_ob, t0, BS, DD, DD, false);
    add_ln_kernel<<<BS, 256>>>(t0, x1, ln2_g, ln2_b, y);

    // ---------------- FFN ----------------
    launch_gemm(y, ffn_w1, ffn_b1, ffn, BS, DFF, DD, true);
    launch_gemm(ffn, ffn_w2, ffn_b2, t0, BS, DD, DFF, false);
    add_ln_kernel<<<BS, 256>>>(y, t0, ln3_g, ln3_b, out);
}

// round 9
// speedup vs baseline: 3.5377x; 1.0496x over previous
#include <cuda_runtime.h>
#include <cuda_bf16.h>
#include <math.h>
#include <stdint.h>

// Problem constants
#define BB 4
#define SS 1024
#define EE 1024
#define DD 1024
#define HH 16
#define DHH 64
#define DFF 4096
#define LN_EPS 1e-6f

// ----------------------------------------------------------------------------
// Scratch (static device globals; no allocations allowed)
// ----------------------------------------------------------------------------
__device__ float g_q   [BB * SS * DD];
__device__ float g_k   [BB * EE * DD];
__device__ float g_v   [BB * EE * DD];
__device__ float g_ctx [BB * SS * DD];
__device__ float g_t0  [BB * SS * DD];
__device__ float g_x1  [BB * SS * DD];
__device__ float g_y   [BB * SS * DD];
__device__ float g_ffn [BB * SS * DFF];
__device__ float g_scores[(size_t)BB * HH * SS * SS];

// ----------------------------------------------------------------------------
// TF32 mma helpers. Operands are fed as raw fp32 bit patterns: the tensor core
// reads only the tf32-significant bits (truncation), saving all CVT traffic.
// ----------------------------------------------------------------------------
__device__ __forceinline__ void mma_tf32(float* d, const unsigned* a,
                                         const unsigned* b, const float* c) {
    asm("mma.sync.aligned.m16n8k8.row.col.f32.tf32.tf32.f32 "
        "{%0,%1,%2,%3}, {%4,%5,%6,%7}, {%8,%9}, {%10,%11,%12,%13};"
        : "=f"(d[0]), "=f"(d[1]), "=f"(d[2]), "=f"(d[3])
        : "r"(a[0]), "r"(a[1]), "r"(a[2]), "r"(a[3]),
          "r"(b[0]), "r"(b[1]),
          "f"(c[0]), "f"(c[1]), "f"(c[2]), "f"(c[3]));
}

__device__ __forceinline__ void cp_async16(void* smem, const void* gmem) {
    unsigned saddr = (unsigned)__cvta_generic_to_shared(smem);
    asm volatile("cp.async.cg.shared.global [%0], [%1], 16;" :: "r"(saddr), "l"(gmem));
}
#define CP_COMMIT() asm volatile("cp.async.commit_group;")
__device__ __forceinline__ void cp_wait0() { asm volatile("cp.async.wait_group 0;"); }
__device__ __forceinline__ void cp_wait1() { asm volatile("cp.async.wait_group 1;"); }

// ----------------------------------------------------------------------------
// TF32 GEMM, 2-stage cp.async pipeline.
// C[M,N] = A[M,K] @ B[K,N] + bias[N], optional ReLU.
// 128x128x32 CTA tile, 8 warps (4m x 2n), warp tile 32x64.
// Dynamic smem: 2 stages of As[128][36] + Bs[32][136]  (71680 B).
// ----------------------------------------------------------------------------
#define GEMM_SMEM (2 * (128 * 36 + 32 * 136) * 4)
#define AS_OFF(st) ((st) * 128 * 36)
#define BS_OFF(st) (2 * 128 * 36 + (st) * 32 * 136)

template <int RELU>
__global__ __launch_bounds__(256, 2) void gemm_tf32_kernel(
    const float* __restrict__ A, const float* __restrict__ B,
    const float* __restrict__ bias, float* __restrict__ C,
    int M, int N, int K)
{
    extern __shared__ float sm[];

    const int tid  = threadIdx.x;
    const int wid  = tid >> 5;
    const int lane = tid & 31;
    const int g    = lane >> 2;
    const int tig  = lane & 3;
    const int warpM = wid & 3;
    const int warpN = wid >> 2;
    const int m0 = blockIdx.y * 128;
    const int n0 = blockIdx.x * 128;

    float acc[2][8][4];
#pragma unroll
    for (int mt = 0; mt < 2; mt++)
#pragma unroll
        for (int nt = 0; nt < 8; nt++)
#pragma unroll
            for (int i = 0; i < 4; i++) acc[mt][nt][i] = 0.f;

    auto load_stage = [&](int st, int k0) {
        float* As = sm + AS_OFF(st);
        float* Bs = sm + BS_OFF(st);
#pragma unroll
        for (int l = 0; l < 4; l++) {
            int idx = tid + l * 256;
            int m = idx >> 3, s = idx & 7;
            cp_async16(&As[m * 36 + s * 4], &A[(size_t)(m0 + m) * K + k0 + s * 4]);
        }
#pragma unroll
        for (int l = 0; l < 4; l++) {
            int idx = tid + l * 256;
            int kk = idx >> 5, s = idx & 31;
            cp_async16(&Bs[kk * 136 + s * 4], &B[(size_t)(k0 + kk) * N + n0 + s * 4]);
        }
        CP_COMMIT();
    };

    const int T = K >> 5;
    load_stage(0, 0);

    for (int t = 0; t < T; t++) {
        if (t + 1 < T) { load_stage((t + 1) & 1, (t + 1) << 5); cp_wait1(); }
        else           { cp_wait0(); }
        __syncthreads();

        const unsigned* As = reinterpret_cast<const unsigned*>(sm + AS_OFF(t & 1));
        const unsigned* Bs = reinterpret_cast<const unsigned*>(sm + BS_OFF(t & 1));
#pragma unroll
        for (int kk = 0; kk < 32; kk += 8) {
            unsigned af[2][4];
#pragma unroll
            for (int mt = 0; mt < 2; mt++) {
                int r = warpM * 32 + mt * 16 + g;
                af[mt][0] = As[r * 36 + kk + tig];
                af[mt][1] = As[(r + 8) * 36 + kk + tig];
                af[mt][2] = As[r * 36 + kk + tig + 4];
                af[mt][3] = As[(r + 8) * 36 + kk + tig + 4];
            }
            unsigned bf[8][2];
#pragma unroll
            for (int nt = 0; nt < 8; nt++) {
                int c = warpN * 64 + nt * 8 + g;
                bf[nt][0] = Bs[(kk + tig) * 136 + c];
                bf[nt][1] = Bs[(kk + tig + 4) * 136 + c];
            }
#pragma unroll
            for (int mt = 0; mt < 2; mt++)
#pragma unroll
                for (int nt = 0; nt < 8; nt++)
                    mma_tf32(acc[mt][nt], af[mt], bf[nt], acc[mt][nt]);
        }
        __syncthreads();
    }

#pragma unroll
    for (int mt = 0; mt < 2; mt++) {
        int r0 = m0 + warpM * 32 + mt * 16 + g;
#pragma unroll
        for (int nt = 0; nt < 8; nt++) {
            int c0 = n0 + warpN * 64 + nt * 8 + tig * 2;
            float b0 = bias[c0], b1 = bias[c0 + 1];
            float v0 = acc[mt][nt][0] + b0;
            float v1 = acc[mt][nt][1] + b1;
            float v2 = acc[mt][nt][2] + b0;
            float v3 = acc[mt][nt][3] + b1;
            if (RELU) {
                v0 = fmaxf(v0, 0.f); v1 = fmaxf(v1, 0.f);
                v2 = fmaxf(v2, 0.f); v3 = fmaxf(v3, 0.f);
            }
            *reinterpret_cast<float2*>(&C[(size_t)r0 * N + c0])       = make_float2(v0, v1);
            *reinterpret_cast<float2*>(&C[(size_t)(r0 + 8) * N + c0]) = make_float2(v2, v3);
        }
    }
}

// ----------------------------------------------------------------------------
// Attention scores (TF32 mma): S[bh,q,k] = (Q . K)*0.125 + mask*(-1e9)
// Full head dim (64) staged in one shot: Qs[128][68], Ks[128][68].
// Causal fully-masked tiles (k0 > q0+127): NO WORK, NO STORE — softmax
// zero-fills those columns without reading them.
// ----------------------------------------------------------------------------
#define SCORES_SMEM (2 * 128 * 68 * 4)

__global__ __launch_bounds__(256, 2) void attn_scores_tf32(
    const float* __restrict__ Qf, const float* __restrict__ Kf,
    const float* __restrict__ pmask, int mask_mode,
    float* __restrict__ Sout, int Sq, int Skv)
{
    extern __shared__ float sm[];
    float* Qs = sm;
    float* Ks = sm + 128 * 68;

    const int tid  = threadIdx.x;
    const int wid  = tid >> 5;
    const int lane = tid & 31;
    const int g    = lane >> 2;
    const int tig  = lane & 3;
    const int warpM = wid & 3;
    const int warpN = wid >> 2;
    const int bh = blockIdx.z;
    const int b = bh >> 4, h = bh & 15;
    const int q0 = blockIdx.y * 128;
    const int k0 = blockIdx.x * 128;

    // Fully-masked causal tile: nothing to do (softmax writes the zeros).
    if (mask_mode == 0 && k0 > q0 + 127) return;

#pragma unroll
    for (int l = 0; l < 8; l++) {
        int idx = tid + l * 256;
        int m = idx >> 4, s = idx & 15;
        cp_async16(&Qs[m * 68 + s * 4],
                   &Qf[(size_t)(b * Sq + q0 + m) * DD + h * DHH + s * 4]);
    }
#pragma unroll
    for (int l = 0; l < 8; l++) {
        int idx = tid + l * 256;
        int m = idx >> 4, s = idx & 15;
        cp_async16(&Ks[m * 68 + s * 4],
                   &Kf[(size_t)(b * Skv + k0 + m) * DD + h * DHH + s * 4]);
    }
    CP_COMMIT();
    cp_wait0();
    __syncthreads();

    float acc[2][8][4];
#pragma unroll
    for (int mt = 0; mt < 2; mt++)
#pragma unroll
        for (int nt = 0; nt < 8; nt++)
#pragma unroll
            for (int i = 0; i < 4; i++) acc[mt][nt][i] = 0.f;

    const unsigned* Qu = reinterpret_cast<const unsigned*>(Qs);
    const unsigned* Ku = reinterpret_cast<const unsigned*>(Ks);
#pragma unroll
    for (int kk = 0; kk < 64; kk += 8) {
        unsigned af[2][4];
#pragma unroll
        for (int mt = 0; mt < 2; mt++) {
            int r = warpM * 32 + mt * 16 + g;
            af[mt][0] = Qu[r * 68 + kk + tig];
            af[mt][1] = Qu[(r + 8) * 68 + kk + tig];
            af[mt][2] = Qu[r * 68 + kk + tig + 4];
            af[mt][3] = Qu[(r + 8) * 68 + kk + tig + 4];
        }
        unsigned bf[8][2];
#pragma unroll
        for (int nt = 0; nt < 8; nt++) {
            int r = warpN * 64 + nt * 8 + g;
            bf[nt][0] = Ku[r * 68 + kk + tig];
            bf[nt][1] = Ku[r * 68 + kk + tig + 4];
        }
#pragma unroll
        for (int mt = 0; mt < 2; mt++)
#pragma unroll
            for (int nt = 0; nt < 8; nt++)
                mma_tf32(acc[mt][nt], af[mt], bf[nt], acc[mt][nt]);
    }

#pragma unroll
    for (int mt = 0; mt < 2; mt++) {
        int qr0 = q0 + warpM * 32 + mt * 16 + g;
#pragma unroll
        for (int nt = 0; nt < 8; nt++) {
            int kc0 = k0 + warpN * 64 + nt * 8 + tig * 2;
#pragma unroll
            for (int half = 0; half < 2; half++) {
                int q = qr0 + half * 8;
                float v0 = acc[mt][nt][half * 2 + 0] * 0.125f;
                float v1 = acc[mt][nt][half * 2 + 1] * 0.125f;
                if (mask_mode == 0) {
                    if (kc0 > q)     v0 -= 1e9f;
                    if (kc0 + 1 > q) v1 -= 1e9f;
                } else {
                    v0 += pmask[(size_t)b * Skv + kc0] * (-1e9f);
                    v1 += pmask[(size_t)b * Skv + kc0 + 1] * (-1e9f);
                }
                *reinterpret_cast<float2*>(&Sout[((size_t)bh * Sq + q) * Skv + kc0]) =
                    make_float2(v0, v1);
            }
        }
    }
}

// ----------------------------------------------------------------------------
// Row softmax, ncols = 1024. One warp per row.
// causal != 0: row q reads only chunks with start <= q (the rest of the row
// was never written by the scores kernel) and writes zeros there.
// ----------------------------------------------------------------------------
__global__ __launch_bounds__(256) void softmax_rows_kernel(
    float* __restrict__ P, int nrows, int causal)
{
    int row = blockIdx.x * 8 + threadIdx.y;
    if (row >= nrows) return;
    float* p = P + (size_t)row * 1024;
    const int lane = threadIdx.x;
    const int q = row & (SS - 1);
    // number of 32-wide chunks that contain written data
    const int nChunk = causal ? ((q >> 5) + 1) : 32;

    float v[32];
    float mx = -INFINITY;
    for (int i = 0; i < nChunk; i++) {
        v[i] = p[lane + i * 32];
        mx = fmaxf(mx, v[i]);
    }
#pragma unroll
    for (int o = 16; o; o >>= 1) mx = fmaxf(mx, __shfl_xor_sync(0xffffffffu, mx, o));

    float sum = 0.f;
    for (int i = 0; i < nChunk; i++) {
        v[i] = __expf(v[i] - mx);
        sum += v[i];
    }
#pragma unroll
    for (int o = 16; o; o >>= 1) sum += __shfl_xor_sync(0xffffffffu, sum, o);
    float inv = 1.f / sum;
    for (int i = 0; i < nChunk; i++) p[lane + i * 32] = v[i] * inv;
    for (int i = nChunk; i < 32; i++) p[lane + i * 32] = 0.f;
}

// ----------------------------------------------------------------------------
// attn_v (TF32 mma, 2-stage pipeline): ctx = P @ V  (per (b,h))
// ----------------------------------------------------------------------------
#define ATTNV_SMEM (2 * (128 * 36 + 32 * 72) * 4)
#define PS_OFF(st) ((st) * 128 * 36)
#define VS_OFF(st) (2 * 128 * 36 + (st) * 32 * 72)

__global__ __launch_bounds__(256, 2) void attn_v_tf32(
    const float* __restrict__ P, const float* __restrict__ Vf,
    float* __restrict__ ctx, int Sq, int Skv, int mask_mode)
{
    extern __shared__ float sm[];

    const int tid  = threadIdx.x;
    const int wid  = tid >> 5;
    const int lane = tid & 31;
    const int g    = lane >> 2;
    const int tig  = lane & 3;
    const int warpM = wid & 3;
    const int warpN = wid >> 2;
    const int bh = blockIdx.y;
    const int b = bh >> 4, h = bh & 15;
    const int q0 = blockIdx.x * 128;

    const int kEnd = (mask_mode == 0) ? min(Skv, q0 + 128) : Skv;
    const int T = kEnd >> 5;

    float acc[2][4][4];
#pragma unroll
    for (int mt = 0; mt < 2; mt++)
#pragma unroll
        for (int nt = 0; nt < 4; nt++)
#pragma unroll
            for (int i = 0; i < 4; i++) acc[mt][nt][i] = 0.f;

    auto load_stage = [&](int st, int k0) {
        float* Ps = sm + PS_OFF(st);
        float* Vs = sm + VS_OFF(st);
#pragma unroll
        for (int l = 0; l < 4; l++) {
            int idx = tid + l * 256;
            int m = idx >> 3, s = idx & 7;
            cp_async16(&Ps[m * 36 + s * 4],
                       &P[((size_t)bh * Sq + q0 + m) * Skv + k0 + s * 4]);
        }
#pragma unroll
        for (int l = 0; l < 2; l++) {
            int idx = tid + l * 256;
            int kk = idx >> 4, s = idx & 15;
            cp_async16(&Vs[kk * 72 + s * 4],
                       &Vf[(size_t)(b * Skv + k0 + kk) * DD + h * DHH + s * 4]);
        }
        CP_COMMIT();
    };

    load_stage(0, 0);

    for (int t = 0; t < T; t++) {
        if (t + 1 < T) { load_stage((t + 1) & 1, (t + 1) << 5); cp_wait1(); }
        else           { cp_wait0(); }
        __syncthreads();

        const unsigned* Ps = reinterpret_cast<const unsigned*>(sm + PS_OFF(t & 1));
        const unsigned* Vs = reinterpret_cast<const unsigned*>(sm + VS_OFF(t & 1));
#pragma unroll
        for (int kk = 0; kk < 32; kk += 8) {
            unsigned af[2][4];
#pragma unroll
            for (int mt = 0; mt < 2; mt++) {
                int r = warpM * 32 + mt * 16 + g;
                af[mt][0] = Ps[r * 36 + kk + tig];
                af[mt][1] = Ps[(r + 8) * 36 + kk + tig];
                af[mt][2] = Ps[r * 36 + kk + tig + 4];
                af[mt][3] = Ps[(r + 8) * 36 + kk + tig + 4];
            }
            unsigned bf[4][2];
#pragma unroll
            for (int nt = 0; nt < 4; nt++) {
                int c = warpN * 32 + nt * 8 + g;
                bf[nt][0] = Vs[(kk + tig) * 72 + c];
                bf[nt][1] = Vs[(kk + tig + 4) * 72 + c];
            }
#pragma unroll
            for (int mt = 0; mt < 2; mt++)
#pragma unroll
                for (int nt = 0; nt < 4; nt++)
                    mma_tf32(acc[mt][nt], af[mt], bf[nt], acc[mt][nt]);
        }
        __syncthreads();
    }

#pragma unroll
    for (int mt = 0; mt < 2; mt++) {
        int qr0 = q0 + warpM * 32 + mt * 16 + g;
#pragma unroll
        for (int nt = 0; nt < 4; nt++) {
            int c0 = warpN * 32 + nt * 8 + tig * 2;
            *reinterpret_cast<float2*>(
                &ctx[(size_t)(b * Sq + qr0) * DD + h * DHH + c0]) =
                make_float2(acc[mt][nt][0], acc[mt][nt][1]);
            *reinterpret_cast<float2*>(
                &ctx[(size_t)(b * Sq + qr0 + 8) * DD + h * DHH + c0]) =
                make_float2(acc[mt][nt][2], acc[mt][nt][3]);
        }
    }
}

// ----------------------------------------------------------------------------
// out[row,:] = LayerNorm(a[row,:] + b[row,:]) * g + beta   (D = 1024)
// ----------------------------------------------------------------------------
__global__ __launch_bounds__(256) void add_ln_kernel(
    const float* __restrict__ a, const float* __restrict__ b,
    const float* __restrict__ g, const float* __restrict__ be,
    float* __restrict__ o)
{
    const int row = blockIdx.x;
    const int tid = threadIdx.x;
    const float* pa = a + (size_t)row * DD;
    const float* pb = b + (size_t)row * DD;

    __shared__ float red[8];
    float v[4];
    float s = 0.f;
#pragma unroll
    for (int i = 0; i < 4; i++) {
        int c = tid + i * 256;
        v[i] = pa[c] + pb[c];
        s += v[i];
    }
#pragma unroll
    for (int o2 = 16; o2; o2 >>= 1) s += __shfl_xor_sync(0xffffffffu, s, o2);
    if ((tid & 31) == 0) red[tid >> 5] = s;
    __syncthreads();
    if (tid < 32) {
        float t = (tid < 8) ? red[tid] : 0.f;
#pragma unroll
        for (int o2 = 4; o2; o2 >>= 1) t += __shfl_xor_sync(0xffffffffu, t, o2);
        if (tid == 0) red[0] = t;
    }
    __syncthreads();
    const float mu = red[0] * (1.f / 1024.f);
    __syncthreads();

    float s2 = 0.f;
#pragma unroll
    for (int i = 0; i < 4; i++) {
        float d = v[i] - mu;
        s2 += d * d;
    }
#pragma unroll
    for (int o2 = 16; o2; o2 >>= 1) s2 += __shfl_xor_sync(0xffffffffu, s2, o2);
    if ((tid & 31) == 0) red[tid >> 5] = s2;
    __syncthreads();
    if (tid < 32) {
        float t = (tid < 8) ? red[tid] : 0.f;
#pragma unroll
        for (int o2 = 4; o2; o2 >>= 1) t += __shfl_xor_sync(0xffffffffu, t, o2);
        if (tid == 0) red[0] = t;
    }
    __syncthreads();
    const float rstd = rsqrtf(red[0] * (1.f / 1024.f) + LN_EPS);

#pragma unroll
    for (int i = 0; i < 4; i++) {
        int c = tid + i * 256;
        o[(size_t)row * DD + c] = (v[i] - mu) * rstd * g[c] + be[c];
    }
}

// ----------------------------------------------------------------------------
// Host launch
// ----------------------------------------------------------------------------
static void launch_gemm(const float* A, const float* B, const float* bias,
                        float* C, int M, int N, int K, bool relu)
{
    dim3 grid(N / 128, M / 128);
    if (relu)
        gemm_tf32_kernel<1><<<grid, 256, GEMM_SMEM>>>(A, B, bias, C, M, N, K);
    else
        gemm_tf32_kernel<0><<<grid, 256, GEMM_SMEM>>>(A, B, bias, C, M, N, K);
}

extern "C" void kernel_launch(void* const* d_in, const int* in_sizes, int n_in,
                              void* d_out, int out_size)
{
    cudaFuncSetAttribute(gemm_tf32_kernel<0>,
                         cudaFuncAttributeMaxDynamicSharedMemorySize, GEMM_SMEM);
    cudaFuncSetAttribute(gemm_tf32_kernel<1>,
                         cudaFuncAttributeMaxDynamicSharedMemorySize, GEMM_SMEM);
    cudaFuncSetAttribute(attn_scores_tf32,
                         cudaFuncAttributeMaxDynamicSharedMemorySize, SCORES_SMEM);
    cudaFuncSetAttribute(attn_v_tf32,
                         cudaFuncAttributeMaxDynamicSharedMemorySize, ATTNV_SMEM);

    const float* x      = (const float*)d_in[0];
    const float* enc    = (const float*)d_in[1];
    const float* causal = (const float*)d_in[2];
    const float* pmask  = (const float*)d_in[3];
    (void)causal;

    const float* m1_wq = (const float*)d_in[4];
    const float* m1_qb = (const float*)d_in[5];
    const float* m1_wk = (const float*)d_in[6];
    const float* m1_kb = (const float*)d_in[7];
    const float* m1_wv = (const float*)d_in[8];
    const float* m1_vb = (const float*)d_in[9];
    const float* m1_wo = (const float*)d_in[10];
    const float* m1_ob = (const float*)d_in[11];

    const float* m2_wq = (const float*)d_in[12];
    const float* m2_qb = (const float*)d_in[13];
    const float* m2_wk = (const float*)d_in[14];
    const float* m2_kb = (const float*)d_in[15];
    const float* m2_wv = (const float*)d_in[16];
    const float* m2_vb = (const float*)d_in[17];
    const float* m2_wo = (const float*)d_in[18];
    const float* m2_ob = (const float*)d_in[19];

    const float* ffn_w1 = (const float*)d_in[20];
    const float* ffn_b1 = (const float*)d_in[21];
    const float* ffn_w2 = (const float*)d_in[22];
    const float* ffn_b2 = (const float*)d_in[23];

    const float* ln1_g = (const float*)d_in[24];
    const float* ln1_b = (const float*)d_in[25];
    const float* ln2_g = (const float*)d_in[26];
    const float* ln2_b = (const float*)d_in[27];
    const float* ln3_g = (const float*)d_in[28];
    const float* ln3_b = (const float*)d_in[29];

    float* out = (float*)d_out;

    float *q, *k, *v, *ctx, *t0, *x1, *y, *ffn, *scores;
    cudaGetSymbolAddress((void**)&q,      g_q);
    cudaGetSymbolAddress((void**)&k,      g_k);
    cudaGetSymbolAddress((void**)&v,      g_v);
    cudaGetSymbolAddress((void**)&ctx,    g_ctx);
    cudaGetSymbolAddress((void**)&t0,     g_t0);
    cudaGetSymbolAddress((void**)&x1,     g_x1);
    cudaGetSymbolAddress((void**)&y,      g_y);
    cudaGetSymbolAddress((void**)&ffn,    g_ffn);
    cudaGetSymbolAddress((void**)&scores, g_scores);

    const size_t OUTN = (size_t)BB * SS * DD;
    const size_t ATT  = (size_t)BB * HH * SS * SS;
    float* attn1 = ((size_t)out_size >= OUTN + ATT)     ? out + OUTN       : scores;
    float* attn2 = ((size_t)out_size >= OUTN + 2 * ATT) ? out + OUTN + ATT : scores;

    const int BS = BB * SS;
    const int BE = BB * EE;
    const int nrowsAttn = BB * HH * SS;

    // ---------------- MHA1 (masked self-attention) ----------------
    launch_gemm(x, m1_wq, m1_qb, q, BS, DD, DD, false);
    launch_gemm(x, m1_wk, m1_kb, k, BS, DD, DD, false);
    launch_gemm(x, m1_wv, m1_vb, v, BS, DD, DD, false);

    attn_scores_tf32<<<dim3(SS / 128, SS / 128, BB * HH), 256, SCORES_SMEM>>>(
        q, k, pmask, /*mask_mode=*/0, attn1, SS, SS);
    softmax_rows_kernel<<<nrowsAttn / 8, dim3(32, 8)>>>(attn1, nrowsAttn, /*causal=*/1);
    attn_v_tf32<<<dim3(SS / 128, BB * HH), 256, ATTNV_SMEM>>>(
        attn1, v, ctx, SS, SS, /*mask_mode=*/0);

    launch_gemm(ctx, m1_wo, m1_ob, t0, BS, DD, DD, false);
    add_ln_kernel<<<BS, 256>>>(x, t0, ln1_g, ln1_b, x1);

    // ---------------- MHA2 (cross-attention) ----------------
    launch_gemm(x1,  m2_wq, m2_qb, q, BS, DD, DD, false);
    launch_gemm(enc, m2_wk, m2_kb, k, BE, DD, DD, false);
    launch_gemm(enc, m2_wv, m2_vb, v, BE, DD, DD, false);

    attn_scores_tf32<<<dim3(EE / 128, SS / 128, BB * HH), 256, SCORES_SMEM>>>(
        q, k, pmask, /*mask_mode=*/1, attn2, SS, EE);
    softmax_rows_kernel<<<nrowsAttn / 8, dim3(32, 8)>>>(attn2, nrowsAttn, /*causal=*/0);
    attn_v_tf32<<<dim3(SS / 128, BB * HH), 256, ATTNV_SMEM>>>(
        attn2, v, ctx, SS, EE, /*mask_mode=*/1);

    launch_gemm(ctx, m2_wo, m2_ob, t0, BS, DD, DD, false);
    add_ln_kernel<<<BS, 256>>>(t0, x1, ln2_g, ln2_b, y);

    // ---------------- FFN ----------------
    launch_gemm(y, ffn_w1, ffn_b1, ffn, BS, DFF, DD, true);
    launch_gemm(ffn, ffn_w2, ffn_b2, t0, BS, DD, DFF, false);
    add_ln_kernel<<<BS, 256>>>(y, t0, ln3_g, ln3_b, out);
}